// round 9
// baseline (speedup 1.0000x reference)
#include <cuda_runtime.h>
#include <cuda_bf16.h>

static constexpr int Bc      = 256;           // batches
static constexpr int Nn      = 512;           // nodes
static constexpr int SUBS    = 16;            // 32-row chunks per batch
static constexpr int SUBROWS = Nn / SUBS;     // 32 rows per work item
static constexpr int ITEMS   = Bc * SUBS;     // 4096 work items
static constexpr int NCTA    = 148 * 4;       // balanced persistent grid
static constexpr int THREADS = 256;
static constexpr int WARPS   = THREADS / 32;  // 8 warps -> 4 rows each per item

// Deterministic partial sums [batch][sub] (no FP atomics anywhere)
__device__ float g_partial[Bc * SUBS];
// Per-batch completion counters (zero-init; self-reset every run)
__device__ int   g_count[Bc];

__global__ __launch_bounds__(THREADS)
void gcn_ilp(const float* __restrict__ x,     // [B, N, 2]
             const float* __restrict__ adj,   // [B, N, N]
             const float* __restrict__ W1,    // [2, 4] row-major
             const float* __restrict__ b1,    // [4]
             const float* __restrict__ W2,    // [4, 1]
             const float* __restrict__ b2,    // [1]
             float* __restrict__ out)         // [B, 1]
{
    const int tid  = threadIdx.x;
    const int lane = tid & 31;
    const int warp = tid >> 5;

    __shared__ float xs0[Nn];         // x[:,0] for current batch
    __shared__ float xs1[Nn];         // x[:,1]
    __shared__ float sW[16];          // [0..7]=W1, [8..11]=b1, [12..15]=W2
    __shared__ float warp_sums[WARPS];
    if (tid < 8)  sW[tid]      = W1[tid];
    if (tid < 4)  sW[8 + tid]  = b1[tid];
    if (tid < 4)  sW[12 + tid] = W2[tid];

    // Contiguous work partition: CTA i owns items [start, end) (6 or 7 each)
    const int start = (int)(((long long)blockIdx.x       * ITEMS) / NCTA);
    const int end   = (int)(((long long)(blockIdx.x + 1) * ITEMS) / NCTA);
    int cur_b = -1;

    for (int w = start; w < end; ++w) {
        const int b   = w >> 4;           // / SUBS
        const int sub = w & (SUBS - 1);

        if (b != cur_b) {                 // uniform across CTA -> safe barriers
            cur_b = b;
            __syncthreads();
            // thread t loads nodes 2t, 2t+1 in one float4 (x interleaved [n][2])
            const float4 v = *(const float4*)(x + (size_t)b * Nn * 2 + tid * 4);
            xs0[tid * 2 + 0] = v.x;  xs1[tid * 2 + 0] = v.y;
            xs0[tid * 2 + 1] = v.z;  xs1[tid * 2 + 1] = v.w;
            __syncthreads();
        }

        // Warp handles 4 contiguous rows: 16 front-batched streaming loads (8 KB)
        const int n0 = sub * SUBROWS + warp * 4;
        const float4* __restrict__ arow =
            (const float4*)(adj + ((size_t)b * Nn + n0) * Nn);

        float4 v[4][4];                   // [row][it]
        #pragma unroll
        for (int r = 0; r < 4; ++r)
            #pragma unroll
            for (int it = 0; it < 4; ++it)
                v[r][it] = __ldcs(arow + r * (Nn / 4) + it * 32 + lane);

        float s0[4] = {0.f, 0.f, 0.f, 0.f};
        float s1[4] = {0.f, 0.f, 0.f, 0.f};
        #pragma unroll
        for (int it = 0; it < 4; ++it) {
            // lane's x operands: contiguous 16B per lane -> conflict-free LDS.128
            const float4 c0 = *(const float4*)(xs0 + it * 128 + lane * 4);
            const float4 c1 = *(const float4*)(xs1 + it * 128 + lane * 4);
            #pragma unroll
            for (int r = 0; r < 4; ++r) {
                s0[r] = fmaf(v[r][it].x, c0.x, s0[r]);  s1[r] = fmaf(v[r][it].x, c1.x, s1[r]);
                s0[r] = fmaf(v[r][it].y, c0.y, s0[r]);  s1[r] = fmaf(v[r][it].y, c1.y, s1[r]);
                s0[r] = fmaf(v[r][it].z, c0.z, s0[r]);  s1[r] = fmaf(v[r][it].z, c1.z, s1[r]);
                s0[r] = fmaf(v[r][it].w, c0.w, s0[r]);  s1[r] = fmaf(v[r][it].w, c1.w, s1[r]);
            }
        }

        // 8 independent 5-stage shuffle chains interleave
        #pragma unroll
        for (int off = 16; off > 0; off >>= 1) {
            #pragma unroll
            for (int r = 0; r < 4; ++r) {
                s0[r] += __shfl_xor_sync(0xFFFFFFFFu, s0[r], off);
                s1[r] += __shfl_xor_sync(0xFFFFFFFFu, s1[r], off);
            }
        }

        if (lane == 0) {
            float p = 0.f;
            #pragma unroll
            for (int r = 0; r < 4; ++r) {
                #pragma unroll
                for (int j = 0; j < 4; ++j) {
                    const float h = fmaf(s0[r], sW[j], fmaf(s1[r], sW[4 + j], sW[8 + j]));
                    p = fmaf(fmaxf(h, 0.0f), sW[12 + j], p);
                }
            }
            warp_sums[warp] = p;          // b2 added per-node in the finalizer
        }
        __syncthreads();

        if (tid == 0) {
            float s = 0.0f;
            #pragma unroll
            for (int ww = 0; ww < WARPS; ++ww) s += warp_sums[ww];
            g_partial[b * SUBS + sub] = s;

            // last-chunk-finishes: int atomic only; FP adds in fixed order.
            __threadfence();
            const int old = atomicAdd(&g_count[b], 1);
            if (old == SUBS - 1) {
                float tot = (float)Nn * __ldcg(b2);
                #pragma unroll
                for (int k = 0; k < SUBS; ++k)
                    tot += __ldcg(&g_partial[b * SUBS + k]);
                out[b] = tot;
                g_count[b] = 0;           // reset for next graph replay
            }
        }
        __syncthreads();                  // protect warp_sums reuse
    }
}

extern "C" void kernel_launch(void* const* d_in, const int* in_sizes, int n_in,
                              void* d_out, int out_size)
{
    const float* x   = (const float*)d_in[0];  // node_features [256,512,2]
    const float* adj = (const float*)d_in[1];  // adj_matrices  [256,512,512]
    const float* W1  = (const float*)d_in[2];  // [2,4]
    const float* b1  = (const float*)d_in[3];  // [4]
    const float* W2  = (const float*)d_in[4];  // [4,1]
    const float* b2  = (const float*)d_in[5];  // [1]
    float* out = (float*)d_out;                // [256,1]

    gcn_ilp<<<NCTA, THREADS>>>(x, adj, W1, b1, W2, b2, out);
}